// round 2
// baseline (speedup 1.0000x reference)
#include <cuda_runtime.h>
#include <math.h>

// Problem constants: x is [2,128,20] fp32 -> 256 tokens of D=20.
// K = 2^20 codes of all +-1 patterns, TEMP = 0.005 (2/TEMP = 400).
// Output: q (5120 floats) then entro_mean, mean_entro, entro_loss, commit_loss.

#define TOK   256
#define DIMS  20
#define HI    1024          // 2^10 patterns per half
#define INV_T2 400.0f       // 2 / TEMP

// Scratch (no cudaMalloc allowed): A[t][c_hi] = exp(-(pen_hi + r_t)),
// B[t][c_lo] = exp(-pen_lo). 1 MB each.
__device__ float g_A[TOK * HI];
__device__ float g_B[TOK * HI];
__device__ double g_acc[3];   // 0: entro_mean sum, 1: mean_entro sum, 2: commit sum

__global__ void k_zero() {
    if (threadIdx.x < 3) g_acc[threadIdx.x] = 0.0;
}

// One block per token: per-dim quantities, q/commit, entropy, and the two
// 1024-entry exp tables for the split-codebook factorization.
__global__ void k_prep(const float* __restrict__ x, float* __restrict__ outq) {
    __shared__ float wh[10];   // wh[b] = w[9-b]   (bit b of c_hi <-> dim 9-b)
    __shared__ float wl[10];   // wl[b] = w[19-b]  (bit b of c_lo <-> dim 19-b)
    __shared__ unsigned sh_hi, sh_lo;
    __shared__ float sh_r;

    const int t   = blockIdx.x;
    const int tid = threadIdx.x;

    if (tid < 32) {
        float Hp = 0.f, rp = 0.f, cp = 0.f;
        unsigned hb = 0;
        if (tid < DIMS) {
            float xv = x[t * DIMS + tid];
            float s  = (xv > 0.f) ? 1.f : -1.f;
            outq[t * DIMS + tid] = s;            // q forward value = hard sign
            float d = xv - s;
            cp = d * d;                           // commit partial
            float ww = INV_T2 * fabsf(xv);        // flip penalty = 2|x|/T
            float e  = expf(-ww);
            rp = log1pf(e);                       // logZ - l_max contribution
            Hp = rp + ww * e / (1.f + e);         // binary entropy of sigmoid(2x/T)
            hb = (xv > 0.f) ? 1u : 0u;
            if (tid < 10) wh[9 - tid] = ww;
            else          wl[19 - tid] = ww;
        }
        // hard-code bits: ballot bit j = sign(x_j); bit-reverse maps dim j
        // to code-bit position (MSB-first per reference shifts).
        unsigned bal = __ballot_sync(0xFFFFFFFFu, hb != 0u);
        unsigned rb  = __brev(bal);
        if (tid == 0) {
            sh_hi = (rb >> 22) & 0x3FFu;          // bits for dims 0..9
            sh_lo = (rb >> 12) & 0x3FFu;          // bits for dims 10..19
        }
        #pragma unroll
        for (int o = 16; o > 0; o >>= 1) {
            Hp += __shfl_down_sync(0xFFFFFFFFu, Hp, o);
            rp += __shfl_down_sync(0xFFFFFFFFu, rp, o);
            cp += __shfl_down_sync(0xFFFFFFFFu, cp, o);
        }
        if (tid == 0) {
            sh_r = rp;
            atomicAdd(&g_acc[0], (double)Hp * (1.0 / 256.0));  // entro_mean term
            atomicAdd(&g_acc[2], (double)cp);                  // commit term
        }
    }
    __syncthreads();

    const unsigned hi = sh_hi, lo = sh_lo;
    const float r = sh_r;
    for (int idx = tid; idx < 2 * HI; idx += blockDim.x) {
        int c = idx & (HI - 1);
        if (idx < HI) {
            unsigned m = (unsigned)c ^ hi;
            float pen = r;
            #pragma unroll
            for (int b = 0; b < 10; b++)
                if ((m >> b) & 1u) pen += wh[b];
            g_A[t * HI + c] = expf(-pen);
        } else {
            unsigned m = (unsigned)c ^ lo;
            float pen = 0.f;
            #pragma unroll
            for (int b = 0; b < 10; b++)
                if ((m >> b) & 1u) pen += wl[b];
            g_B[t * HI + c] = expf(-pen);
        }
    }
}

// M[hi][lo] = sum_t A[t][hi] * B[t][lo]  (1024x1024, K=256),
// fused epilogue: mean_entro partial = sum -m*log(m + 1e-10), m = M/256.
__global__ void k_gemm_entropy() {
    __shared__ float sA[16][64];
    __shared__ float sB[16][64];

    const int bm = blockIdx.x & 15;        // hi tile
    const int bn = blockIdx.x >> 4;        // lo tile
    const int tx = threadIdx.x & 15;
    const int ty = threadIdx.x >> 4;

    float acc[4][4] = {};

    const float* Abase = g_A + bm * 64;
    const float* Bbase = g_B + bn * 64;

    for (int k0 = 0; k0 < TOK; k0 += 16) {
        #pragma unroll
        for (int i = 0; i < 4; i++) {
            int idx = threadIdx.x + i * 256;
            int kk = idx >> 6, mm = idx & 63;
            sA[kk][mm] = Abase[(k0 + kk) * HI + mm];
            sB[kk][mm] = Bbase[(k0 + kk) * HI + mm];
        }
        __syncthreads();
        #pragma unroll
        for (int kk = 0; kk < 16; kk++) {
            float4 a = *(const float4*)&sA[kk][ty * 4];
            float4 b = *(const float4*)&sB[kk][tx * 4];
            acc[0][0] += a.x * b.x; acc[0][1] += a.x * b.y; acc[0][2] += a.x * b.z; acc[0][3] += a.x * b.w;
            acc[1][0] += a.y * b.x; acc[1][1] += a.y * b.y; acc[1][2] += a.y * b.z; acc[1][3] += a.y * b.w;
            acc[2][0] += a.z * b.x; acc[2][1] += a.z * b.y; acc[2][2] += a.z * b.z; acc[2][3] += a.z * b.w;
            acc[3][0] += a.w * b.x; acc[3][1] += a.w * b.y; acc[3][2] += a.w * b.z; acc[3][3] += a.w * b.w;
        }
        __syncthreads();
    }

    // fused entropy epilogue (skip logf for the ~99% zero entries)
    float s = 0.f;
    #pragma unroll
    for (int i = 0; i < 4; i++)
        #pragma unroll
        for (int j = 0; j < 4; j++) {
            float m = acc[i][j] * (1.0f / 256.0f);
            if (m > 0.f) s -= m * logf(m + 1e-10f);
        }

    __shared__ float red[8];
    #pragma unroll
    for (int o = 16; o > 0; o >>= 1) s += __shfl_down_sync(0xFFFFFFFFu, s, o);
    if ((threadIdx.x & 31) == 0) red[threadIdx.x >> 5] = s;
    __syncthreads();
    if (threadIdx.x < 8) {
        float v = red[threadIdx.x];
        #pragma unroll
        for (int o = 4; o > 0; o >>= 1) v += __shfl_down_sync(0xFFu, v, o);
        if (threadIdx.x == 0) atomicAdd(&g_acc[1], (double)v);
    }
}

__global__ void k_finalize(float* __restrict__ out, int qn) {
    double em = g_acc[0];
    double me = g_acc[1];
    double cm = g_acc[2];
    out[qn + 0] = (float)em;                       // entro_mean_s
    out[qn + 1] = (float)me;                       // mean_entro
    out[qn + 2] = (float)(em - me);                // entro_loss (ALPHA = 1)
    out[qn + 3] = (float)(cm / (double)qn);        // commit_loss
}

extern "C" void kernel_launch(void* const* d_in, const int* in_sizes, int n_in,
                              void* d_out, int out_size) {
    const float* x = (const float*)d_in[0];
    float* out = (float*)d_out;
    int qn = in_sizes[0];                          // 5120

    k_zero<<<1, 32>>>();
    k_prep<<<TOK, 256>>>(x, out);
    k_gemm_entropy<<<256, 256>>>();
    k_finalize<<<1, 1>>>(out, qn);
}

// round 4
// speedup vs baseline: 1.9512x; 1.9512x over previous
#include <cuda_runtime.h>
#include <math.h>

// LFQ: x [2,128,20] fp32 -> 256 tokens, D=20, K=2^20, TEMP=0.005.
// Out: q (5120 floats = sign(x)) then entro_mean, mean_entro, entro_loss,
// commit_loss.
//
// Factorization: prob(code c | token t) = exp(-(pen(c,t) + r_t)), pen = sum
// over dims flipped vs hard sign of 2|x_d|/T = 400|x_d|, r_t = sum_d
// log1p(exp(-400|x_d|)). One flip on a typical dim (|x|~0.8) gives pen~320
// -> exp underflows to exactly 0 in fp32 (as it does in the reference's own
// softmax). Survivors need ALL flipped dims with |x_d| < ~0.11 => ~2-4
// nonzero codes per 10-bit half per token. mean_probs over K=2^20 is ~1-4K
// sparse -> scatter cross products into a dense table, entropy over the
// touched set only, then repair the table to zero for graph replay.
//
// Single launch: last-block-done pattern does the global reduction.

#define TOK    256
#define DIMS   20
#define THRESH 45.0f            // exp(-45)=2.9e-20, below fp32 softmax noise
#define MCAP   (1 << 20)

__device__ float    g_M[MCAP];       // zero at load; restored to zero each run
__device__ int      g_touched[MCAP];
__device__ int      g_cnt;           // zero at load; reset by last block
__device__ unsigned g_ticket;        // zero at load; reset by last block
__device__ float    g_pH[TOK];       // per-token entropy sums
__device__ float    g_pC[TOK];       // per-token commit partials

__global__ void __launch_bounds__(256, 8)
k_lfq(const float* __restrict__ x, float* __restrict__ outq,
      float* __restrict__ out4) {
    __shared__ float ww[DIMS];          // 400|x_d|
    __shared__ float s_r;
    __shared__ unsigned s_hi, s_lo;     // hard code bits
    __shared__ int   nA, nB;
    __shared__ int   codeA[1024]; __shared__ float valA[1024];
    __shared__ int   codeB[1024]; __shared__ float valB[1024];
    __shared__ int   s_last;

    const int t = blockIdx.x, tid = threadIdx.x;
    if (tid == 0) { nA = 0; nB = 0; }

    // ---- per-dim stats, q, per-token entropy/commit partials (warp 0) ----
    if (tid < 32) {
        float Hp = 0.f, rp = 0.f, cp = 0.f;
        unsigned hb = 0;
        if (tid < DIMS) {
            float xv = x[t * DIMS + tid];
            float sg = (xv > 0.f) ? 1.f : -1.f;
            outq[t * DIMS + tid] = sg;
            float d = xv - sg;
            cp = d * d;
            float w = 400.0f * fabsf(xv);
            ww[tid] = w;
            float e = expf(-w);
            rp = log1pf(e);                      // logZ - l_max contribution
            Hp = rp + w * e / (1.f + e);         // binary entropy term
            hb = (xv > 0.f) ? 1u : 0u;
        }
        unsigned bal = __ballot_sync(0xFFFFFFFFu, hb != 0u);
        #pragma unroll
        for (int o = 16; o > 0; o >>= 1) {
            Hp += __shfl_down_sync(0xFFFFFFFFu, Hp, o);
            rp += __shfl_down_sync(0xFFFFFFFFu, rp, o);
            cp += __shfl_down_sync(0xFFFFFFFFu, cp, o);
        }
        if (tid == 0) {
            s_hi = bal & 0x3FFu;                 // dims 0..9
            s_lo = (bal >> 10) & 0x3FFu;         // dims 10..19
            s_r  = rp;
            g_pH[t] = Hp;
            g_pC[t] = cp;
        }
    }
    __syncthreads();

    // ---- enumerate survivor codes for both 10-bit halves ----
    const float r = s_r;
    for (int idx = tid; idx < 2048; idx += blockDim.x) {
        const int half = idx >> 10;
        const int m = idx & 1023;
        const float* w = ww + half * 10;
        float pen = 0.f;
        #pragma unroll
        for (int b = 0; b < 10; b++)
            if ((m >> b) & 1) pen += w[b];
        if (half == 0) {
            if (pen + r < THRESH) {
                int p = atomicAdd(&nA, 1);
                codeA[p] = (int)(s_hi ^ (unsigned)m);
                valA[p]  = expf(-(pen + r));
            }
        } else {
            if (pen < THRESH) {
                int p = atomicAdd(&nB, 1);
                codeB[p] = (int)(s_lo ^ (unsigned)m);
                valB[p]  = expf(-pen);
            }
        }
    }
    __syncthreads();

    // ---- sparse scatter of the cross product into the 2^20 table ----
    const int na = nA, nb = nB;
    const int total = na * nb;
    for (int k = tid; k < total; k += blockDim.x) {
        int i = k / nb, j = k - i * nb;
        float v = valA[i] * valB[j];
        if (v > 0.f) {
            int idx = codeA[i] * 1024 + codeB[j];
            float old = atomicAdd(&g_M[idx], v);
            if (old == 0.0f) {                   // exactly one first-toucher
                int p = atomicAdd(&g_cnt, 1);
                g_touched[p] = idx;
            }
        }
    }

    // ---- last-block-done: final reduction in the block drawing ticket 255 ----
    __syncthreads();
    if (tid == 0) {
        __threadfence();
        unsigned tk = atomicAdd(&g_ticket, 1u);
        s_last = (tk == TOK - 1u);
    }
    __syncthreads();
    if (!s_last) return;

    __threadfence();                             // acquire all blocks' writes
    __shared__ int s_n;
    if (tid == 0) s_n = g_cnt;
    __syncthreads();
    const int n = s_n;

    float s = 0.f;
    for (int i = tid; i < n; i += blockDim.x) {
        int idx = g_touched[i];
        float m = g_M[idx] * (1.0f / 256.0f);
        if (m > 0.f) s -= m * logf(m + 1e-10f);
        g_M[idx] = 0.0f;                         // repair for next replay
    }
    float h = g_pH[tid], c = g_pC[tid];          // 256 threads == TOK

    __shared__ float rs[8], rh[8], rc[8];
    #pragma unroll
    for (int o = 16; o > 0; o >>= 1) {
        s += __shfl_down_sync(0xFFFFFFFFu, s, o);
        h += __shfl_down_sync(0xFFFFFFFFu, h, o);
        c += __shfl_down_sync(0xFFFFFFFFu, c, o);
    }
    if ((tid & 31) == 0) { rs[tid >> 5] = s; rh[tid >> 5] = h; rc[tid >> 5] = c; }
    __syncthreads();
    if (tid < 8) {
        float vs = rs[tid], vh = rh[tid], vc = rc[tid];
        #pragma unroll
        for (int o = 4; o > 0; o >>= 1) {
            vs += __shfl_down_sync(0xFFu, vs, o);
            vh += __shfl_down_sync(0xFFu, vh, o);
            vc += __shfl_down_sync(0xFFu, vc, o);
        }
        if (tid == 0) {
            g_cnt = 0;
            g_ticket = 0u;
            float em = vh * (1.0f / 256.0f);     // entro_mean_s
            out4[0] = em;
            out4[1] = vs;                        // mean_entro
            out4[2] = em - vs;                   // entro_loss (ALPHA = 1)
            out4[3] = vc * (1.0f / 5120.0f);     // commit_loss
        }
    }
}

extern "C" void kernel_launch(void* const* d_in, const int* in_sizes, int n_in,
                              void* d_out, int out_size) {
    const float* x = (const float*)d_in[0];
    float* out = (float*)d_out;
    int qn = in_sizes[0];                        // 5120

    k_lfq<<<TOK, 256>>>(x, out, out + qn);
}

// round 7
// speedup vs baseline: 1.9806x; 1.0151x over previous
#include <cuda_runtime.h>
#include <math.h>

// LFQ: x [2,128,20] fp32 -> 256 tokens, D=20, K=2^20, TEMP=0.005.
// Out: q (5120 floats = sign(x)) then entro_mean, mean_entro, entro_loss,
// commit_loss.
//
// prob(code c | t) = exp(-(pen(c,t) + r_t)); pen = sum of 400|x_d| over dims
// flipped vs hard sign; r_t = sum_d log1p(exp(-400|x_d|)). A flip on a
// typical dim underflows exp to 0 in fp32 (as in the reference softmax), so
// only ~2-4 codes per 10-bit half survive per token. mean_probs is ~1-4K
// sparse over 2^20 -> scatter cross products into a dense table, entropy over
// the touched set, repair table to zero for graph replay. Single launch with
// last-block-done reduction. g_cnt allocation is warp-aggregated to kill the
// single-address atomic serialization seen in R4.

#define TOK    256
#define DIMS   20
#define THRESH 45.0f            // exp(-45)=2.9e-20, below fp32 softmax noise
#define MCAP   (1 << 20)

__device__ float    g_M[MCAP];       // zero at load; restored to zero each run
__device__ int      g_touched[MCAP];
__device__ int      g_cnt;           // zero at load; reset by last block
__device__ unsigned g_ticket;        // zero at load; reset by last block
__device__ float    g_pH[TOK];       // per-token entropy sums
__device__ float    g_pC[TOK];       // per-token commit partials

__global__ void __launch_bounds__(256, 8)
k_lfq(const float* __restrict__ x, float* __restrict__ outq,
      float* __restrict__ out4) {
    __shared__ float ww[DIMS];          // 400|x_d|
    __shared__ float s_r;
    __shared__ unsigned s_hi, s_lo;     // hard code bits
    __shared__ int   nA, nB;
    __shared__ int   codeA[1024]; __shared__ float valA[1024];
    __shared__ int   codeB[1024]; __shared__ float valB[1024];
    __shared__ int   s_last;

    const int t = blockIdx.x, tid = threadIdx.x;
    const int lane = tid & 31;
    if (tid == 0) { nA = 0; nB = 0; }

    // ---- per-dim stats, q, per-token entropy/commit partials (warp 0) ----
    if (tid < 32) {
        float Hp = 0.f, rp = 0.f, cp = 0.f;
        unsigned hb = 0;
        if (tid < DIMS) {
            float xv = x[t * DIMS + tid];
            float sg = (xv > 0.f) ? 1.f : -1.f;
            outq[t * DIMS + tid] = sg;
            float d = xv - sg;
            cp = d * d;
            float w = 400.0f * fabsf(xv);
            ww[tid] = w;
            float e = expf(-w);
            rp = log1pf(e);                      // logZ - l_max contribution
            Hp = rp + w * e / (1.f + e);         // binary entropy term
            hb = (xv > 0.f) ? 1u : 0u;
        }
        unsigned bal = __ballot_sync(0xFFFFFFFFu, hb != 0u);
        #pragma unroll
        for (int o = 16; o > 0; o >>= 1) {
            Hp += __shfl_down_sync(0xFFFFFFFFu, Hp, o);
            rp += __shfl_down_sync(0xFFFFFFFFu, rp, o);
            cp += __shfl_down_sync(0xFFFFFFFFu, cp, o);
        }
        if (tid == 0) {
            s_hi = bal & 0x3FFu;                 // dims 0..9
            s_lo = (bal >> 10) & 0x3FFu;         // dims 10..19
            s_r  = rp;
            g_pH[t] = Hp;
            g_pC[t] = cp;
        }
    }
    __syncthreads();

    // ---- enumerate survivor codes for both 10-bit halves ----
    const float r = s_r;
    for (int idx = tid; idx < 2048; idx += blockDim.x) {
        const int half = idx >> 10;
        const int m = idx & 1023;
        const float* w = ww + half * 10;
        float pen = 0.f;
        #pragma unroll
        for (int b = 0; b < 10; b++)
            if ((m >> b) & 1) pen += w[b];
        if (half == 0) {
            if (pen + r < THRESH) {
                int p = atomicAdd(&nA, 1);
                codeA[p] = (int)(s_hi ^ (unsigned)m);
                valA[p]  = __expf(-(pen + r));
            }
        } else {
            if (pen < THRESH) {
                int p = atomicAdd(&nB, 1);
                codeB[p] = (int)(s_lo ^ (unsigned)m);
                valB[p]  = __expf(-pen);
            }
        }
    }
    __syncthreads();

    // ---- sparse scatter; warp-aggregated touched-list allocation ----
    const int na = nA, nb = nB;
    const int total = na * nb;
    for (int k0 = 0; k0 < total; k0 += 256) {    // uniform bound for all threads
        const int k = k0 + tid;
        bool need = false;
        int idx = 0;
        if (k < total) {
            int i = k / nb, j = k - i * nb;
            float v = valA[i] * valB[j];
            if (v > 0.f) {
                idx = codeA[i] * 1024 + codeB[j];
                float old = atomicAdd(&g_M[idx], v);
                need = (old == 0.0f);            // exactly one first-toucher
            }
        }
        unsigned ball = __ballot_sync(0xFFFFFFFFu, need);
        if (ball) {
            int leader = __ffs(ball) - 1;
            int base = 0;
            if (lane == leader) base = atomicAdd(&g_cnt, __popc(ball));
            base = __shfl_sync(0xFFFFFFFFu, base, leader);
            if (need)
                g_touched[base + __popc(ball & ((1u << lane) - 1u))] = idx;
        }
    }

    // ---- last-block-done: reduction in the block drawing ticket 255 ----
    __syncthreads();
    if (tid == 0) {
        __threadfence();
        unsigned tk = atomicAdd(&g_ticket, 1u);
        s_last = (tk == TOK - 1u);
    }
    __syncthreads();
    if (!s_last) return;

    __threadfence();                             // acquire all blocks' writes
    __shared__ int s_n;
    if (tid == 0) s_n = g_cnt;
    __syncthreads();
    const int n = s_n;

    float s = 0.f;
    #pragma unroll 4
    for (int i = tid; i < n; i += 256) {
        int idx = g_touched[i];
        float m = g_M[idx] * (1.0f / 256.0f);
        if (m > 0.f) s -= m * __logf(m + 1e-10f);
        g_M[idx] = 0.0f;                         // repair for next replay
    }
    float h = g_pH[tid], c = g_pC[tid];          // 256 threads == TOK

    __shared__ float rs[8], rh[8], rc[8];
    #pragma unroll
    for (int o = 16; o > 0; o >>= 1) {
        s += __shfl_down_sync(0xFFFFFFFFu, s, o);
        h += __shfl_down_sync(0xFFFFFFFFu, h, o);
        c += __shfl_down_sync(0xFFFFFFFFu, c, o);
    }
    if (lane == 0) { rs[tid >> 5] = s; rh[tid >> 5] = h; rc[tid >> 5] = c; }
    __syncthreads();
    if (tid < 8) {
        float vs = rs[tid], vh = rh[tid], vc = rc[tid];
        #pragma unroll
        for (int o = 4; o > 0; o >>= 1) {
            vs += __shfl_down_sync(0xFFu, vs, o);
            vh += __shfl_down_sync(0xFFu, vh, o);
            vc += __shfl_down_sync(0xFFu, vc, o);
        }
        if (tid == 0) {
            g_cnt = 0;
            g_ticket = 0u;
            float em = vh * (1.0f / 256.0f);     // entro_mean_s
            out4[0] = em;
            out4[1] = vs;                        // mean_entro
            out4[2] = em - vs;                   // entro_loss (ALPHA = 1)
            out4[3] = vc * (1.0f / 5120.0f);     // commit_loss
        }
    }
}

extern "C" void kernel_launch(void* const* d_in, const int* in_sizes, int n_in,
                              void* d_out, int out_size) {
    const float* x = (const float*)d_in[0];
    float* out = (float*)d_out;
    int qn = in_sizes[0];                        // 5120

    k_lfq<<<TOK, 256>>>(x, out, out + qn);
}

// round 11
// speedup vs baseline: 2.3033x; 1.1629x over previous
#include <cuda_runtime.h>
#include <math.h>

// LFQ: x [2,128,20] fp32 -> 256 tokens, D=20, K=2^20, TEMP=0.005.
// Out: q (5120 floats = sign(x)) then entro_mean, mean_entro, entro_loss,
// commit_loss.
//
// prob(code c | t) = exp(-(pen(c,t) + r_t)); pen = sum of 400|x_d| over dims
// flipped vs hard sign; r_t = sum_d log1p(exp(-400|x_d|)). A flip on a
// typical dim underflows exp to 0 in fp32 (as in the reference's own
// softmax), so only ~2-4 codes per 10-bit half survive per token.
//
// R8 design: no touched-list. Phase 1 scatters with RETURN-FREE float atomics
// (REDG, no latency chain). Grid barrier (ticket + volatile spin; all 256
// CTAs co-resident). Phase 2: every block scans + zeroes its 16KB slice of
// the 4MB table (dense float4 traffic at LTS rate ~ cheap), entropy of the
// rare nonzeros, double-REDG reduction, last block finalizes and resets.

#define TOK    256
#define DIMS   20
#define THRESH 45.0f            // exp(-45)=2.9e-20, below fp32 softmax noise
#define MCAP   (1 << 20)
#define SEGF4  1024             // float4s per block slice (4096 floats)

__device__ float    g_M[MCAP];       // zero at load; re-zeroed every run
__device__ unsigned g_t1;            // phase-1 arrival ticket
__device__ unsigned g_t2;            // phase-2 arrival ticket
__device__ double   g_accH;          // sum of per-token entropies
__device__ double   g_accC;          // sum of commit partials
__device__ double   g_accS;          // mean_probs entropy sum

__global__ void __launch_bounds__(256, 4)
k_lfq(const float* __restrict__ x, float* __restrict__ outq,
      float* __restrict__ out4) {
    __shared__ float ww[DIMS];          // 400|x_d|
    __shared__ float s_r;
    __shared__ unsigned s_hi, s_lo;     // hard code bits
    __shared__ int   nA, nB;
    __shared__ int   codeA[1024]; __shared__ float valA[1024];
    __shared__ int   codeB[1024]; __shared__ float valB[1024];
    __shared__ int   s_fin;

    const int t = blockIdx.x, tid = threadIdx.x;
    const int lane = tid & 31;
    if (tid == 0) { nA = 0; nB = 0; }

    // ---- phase 1a: per-dim stats, q, H/commit partials (warp 0) ----
    if (tid < 32) {
        float Hp = 0.f, rp = 0.f, cp = 0.f;
        unsigned hb = 0;
        if (tid < DIMS) {
            float xv = x[t * DIMS + tid];
            float sg = (xv > 0.f) ? 1.f : -1.f;
            outq[t * DIMS + tid] = sg;
            float d = xv - sg;
            cp = d * d;
            float w = 400.0f * fabsf(xv);
            ww[tid] = w;
            float e = __expf(-w);
            rp = __logf(1.0f + e);               // logZ - l_max contribution
            Hp = rp + w * e / (1.f + e);         // binary entropy term
            hb = (xv > 0.f) ? 1u : 0u;
        }
        unsigned bal = __ballot_sync(0xFFFFFFFFu, hb != 0u);
        #pragma unroll
        for (int o = 16; o > 0; o >>= 1) {
            Hp += __shfl_down_sync(0xFFFFFFFFu, Hp, o);
            rp += __shfl_down_sync(0xFFFFFFFFu, rp, o);
            cp += __shfl_down_sync(0xFFFFFFFFu, cp, o);
        }
        if (tid == 0) {
            s_hi = bal & 0x3FFu;                 // dims 0..9
            s_lo = (bal >> 10) & 0x3FFu;         // dims 10..19
            s_r  = rp;
            atomicAdd(&g_accH, (double)Hp);      // REDG.64, no return
            atomicAdd(&g_accC, (double)cp);
        }
    }
    __syncthreads();

    // ---- phase 1b: enumerate survivor codes for both 10-bit halves ----
    const float r = s_r;
    for (int idx = tid; idx < 2048; idx += blockDim.x) {
        const int half = idx >> 10;
        const int m = idx & 1023;
        const float* w = ww + half * 10;
        float pen = 0.f;
        #pragma unroll
        for (int b = 0; b < 10; b++)
            if ((m >> b) & 1) pen += w[b];
        if (half == 0) {
            if (pen + r < THRESH) {
                int p = atomicAdd(&nA, 1);
                codeA[p] = (int)(s_hi ^ (unsigned)m);
                valA[p]  = __expf(-(pen + r));
            }
        } else {
            if (pen < THRESH) {
                int p = atomicAdd(&nB, 1);
                codeB[p] = (int)(s_lo ^ (unsigned)m);
                valB[p]  = __expf(-pen);
            }
        }
    }
    __syncthreads();

    // ---- phase 1c: scatter cross product; return-free atomics (REDG) ----
    const int na = nA, nb = nB;
    const int total = na * nb;
    for (int k = tid; k < total; k += 256) {
        int i = k / nb, j = k - i * nb;
        float v = valA[i] * valB[j];
        if (v > 0.f)
            atomicAdd(&g_M[codeA[i] * 1024 + codeB[j]], v);
    }

    // ---- grid barrier: arrive, then spin until all 256 arrived ----
    __syncthreads();
    if (tid == 0) {
        __threadfence();
        atomicAdd(&g_t1, 1u);                    // REDG, no return
        while (*(volatile unsigned*)&g_t1 < (unsigned)TOK)
            __nanosleep(64);
    }
    __syncthreads();
    __threadfence();                             // acquire other blocks' writes

    // ---- phase 2: scan + zero this block's 16KB slice of the table ----
    float s = 0.f;
    {
        float4* seg = (float4*)(g_M + blockIdx.x * (SEGF4 * 4));
        const float4 z4 = make_float4(0.f, 0.f, 0.f, 0.f);
        #pragma unroll
        for (int i = 0; i < 4; i++) {
            int off = tid + i * 256;
            float4 v = __ldcv(seg + off);        // L2-fresh (bypass L1)
            if (v.x > 0.f) s -= v.x * (1.0f/256.0f) * __logf(v.x * (1.0f/256.0f) + 1e-10f);
            if (v.y > 0.f) s -= v.y * (1.0f/256.0f) * __logf(v.y * (1.0f/256.0f) + 1e-10f);
            if (v.z > 0.f) s -= v.z * (1.0f/256.0f) * __logf(v.z * (1.0f/256.0f) + 1e-10f);
            if (v.w > 0.f) s -= v.w * (1.0f/256.0f) * __logf(v.w * (1.0f/256.0f) + 1e-10f);
            seg[off] = z4;                       // repair for next replay
        }
    }

    // block-reduce s, one double REDG per block
    __shared__ float rs[8];
    #pragma unroll
    for (int o = 16; o > 0; o >>= 1)
        s += __shfl_down_sync(0xFFFFFFFFu, s, o);
    if (lane == 0) rs[tid >> 5] = s;
    __syncthreads();
    if (tid == 0) {
        float v = rs[0] + rs[1] + rs[2] + rs[3] + rs[4] + rs[5] + rs[6] + rs[7];
        atomicAdd(&g_accS, (double)v);
        __threadfence();
        unsigned tk = atomicAdd(&g_t2, 1u);      // needs return (elect last)
        s_fin = (tk == TOK - 1u);
    }
    __syncthreads();
    if (!s_fin) return;

    // ---- finalize (last block, thread 0) ----
    if (tid == 0) {
        __threadfence();
        double vh = *(volatile double*)&g_accH;
        double vc = *(volatile double*)&g_accC;
        double vs = *(volatile double*)&g_accS;
        double em = vh * (1.0 / 256.0);          // entro_mean_s
        out4[0] = (float)em;
        out4[1] = (float)vs;                     // mean_entro
        out4[2] = (float)(em - vs);              // entro_loss (ALPHA = 1)
        out4[3] = (float)(vc * (1.0 / 5120.0));  // commit_loss
        g_t1 = 0u; g_t2 = 0u;                    // reset for next replay
        g_accH = 0.0; g_accC = 0.0; g_accS = 0.0;
    }
}

extern "C" void kernel_launch(void* const* d_in, const int* in_sizes, int n_in,
                              void* d_out, int out_size) {
    const float* x = (const float*)d_in[0];
    float* out = (float*)d_out;
    int qn = in_sizes[0];                        // 5120

    k_lfq<<<TOK, 256>>>(x, out, out + qn);
}

// round 12
// speedup vs baseline: 2.6715x; 1.1599x over previous
#include <cuda_runtime.h>
#include <math.h>

// LFQ: x [2,128,20] fp32 -> 256 tokens, D=20, K=2^20, TEMP=0.005.
// Out: q (5120 floats = sign(x)) then entro_mean, mean_entro, entro_loss,
// commit_loss.
//
// prob(code c|t) = exp(-(pen + r_t)); pen = sum of 400|x_d| over dims flipped
// vs the hard sign code. Flips on typical dims underflow exp to exactly 0 in
// fp32 (as in the reference softmax), so only ~2-4 codes per 10-bit half
// survive per token; mean_probs over 2^20 is ~1-4K sparse.
//
// R12: single launch, NO grid barrier, NO table scan/repair.
//  - Each slot of the code table packs {epoch:u32, val:f32}; tag != g_epoch
//    means "zero". The last block bumps g_epoch, so graph replays see a
//    logically clean table without any re-zeroing pass.
//  - Entropy is computed DURING the scatter: each successful CAS that takes a
//    slot from v_old to v_new contributes f(v_new) - f(v_old), where
//    f(v) = -(v/256)log(v/256 + 1e-10). Per-code contributions telescope to
//    f(final): exact for any interleaving, collisions included.
//  - Block partial sums REDG into doubles; a return-atomic ticket elects the
//    last block, which writes the 4 scalars and resets state.

#define TOK    256
#define DIMS   20
#define THRESH 45.0f            // exp(-45)=2.9e-20, below fp32 softmax noise
#define MCAP   (1 << 20)

__device__ unsigned long long g_T[MCAP];  // {epoch, val} slots; zero at load
__device__ unsigned g_epoch = 1u;         // current-launch tag (tag 0 = clean)
__device__ unsigned g_ticket;             // finalize election; reset each run
__device__ double   g_accH;               // sum of per-token entropies
__device__ double   g_accC;               // sum of commit partials
__device__ double   g_accS;               // mean_probs entropy sum

__device__ __forceinline__ float entf(float v) {
    // f(v) = -(v/256) * log(v/256 + 1e-10); f(0) = 0
    float m = v * (1.0f / 256.0f);
    return (m > 0.f) ? -m * __logf(m + 1e-10f) : 0.f;
}

__global__ void __launch_bounds__(256, 4)
k_lfq(const float* __restrict__ x, float* __restrict__ outq,
      float* __restrict__ out4) {
    __shared__ float ww[DIMS];          // 400|x_d|
    __shared__ float s_r;
    __shared__ unsigned s_hi, s_lo;     // hard code bits
    __shared__ unsigned s_ep;
    __shared__ int   nA, nB;
    __shared__ int   codeA[1024]; __shared__ float valA[1024];
    __shared__ int   codeB[1024]; __shared__ float valB[1024];

    const int t = blockIdx.x, tid = threadIdx.x;
    const int lane = tid & 31;
    if (tid == 0) { nA = 0; nB = 0; s_ep = g_epoch; }

    // ---- phase 1a: per-dim stats, q, H/commit partials (warp 0) ----
    if (tid < 32) {
        float Hp = 0.f, rp = 0.f, cp = 0.f;
        unsigned hb = 0;
        if (tid < DIMS) {
            float xv = x[t * DIMS + tid];
            float sg = (xv > 0.f) ? 1.f : -1.f;
            outq[t * DIMS + tid] = sg;
            float d = xv - sg;
            cp = d * d;
            float w = 400.0f * fabsf(xv);
            ww[tid] = w;
            float e = __expf(-w);
            rp = __logf(1.0f + e);               // logZ - l_max contribution
            Hp = rp + w * e / (1.f + e);         // binary entropy term
            hb = (xv > 0.f) ? 1u : 0u;
        }
        unsigned bal = __ballot_sync(0xFFFFFFFFu, hb != 0u);
        #pragma unroll
        for (int o = 16; o > 0; o >>= 1) {
            Hp += __shfl_down_sync(0xFFFFFFFFu, Hp, o);
            rp += __shfl_down_sync(0xFFFFFFFFu, rp, o);
            cp += __shfl_down_sync(0xFFFFFFFFu, cp, o);
        }
        if (tid == 0) {
            s_hi = bal & 0x3FFu;                 // dims 0..9
            s_lo = (bal >> 10) & 0x3FFu;         // dims 10..19
            s_r  = rp;
            atomicAdd(&g_accH, (double)Hp);      // REDG.64, no return
            atomicAdd(&g_accC, (double)cp);
        }
    }
    __syncthreads();

    // ---- phase 1b: enumerate survivor codes for both 10-bit halves ----
    const float r = s_r;
    for (int idx = tid; idx < 2048; idx += blockDim.x) {
        const int half = idx >> 10;
        const int m = idx & 1023;
        const float* w = ww + half * 10;
        float pen = 0.f;
        #pragma unroll
        for (int b = 0; b < 10; b++)
            if ((m >> b) & 1) pen += w[b];
        if (half == 0) {
            if (pen + r < THRESH) {
                int p = atomicAdd(&nA, 1);
                codeA[p] = (int)(s_hi ^ (unsigned)m);
                valA[p]  = __expf(-(pen + r));
            }
        } else {
            if (pen < THRESH) {
                int p = atomicAdd(&nB, 1);
                codeB[p] = (int)(s_lo ^ (unsigned)m);
                valB[p]  = __expf(-pen);
            }
        }
    }
    __syncthreads();

    // ---- phase 1c: CAS scatter with telescoping entropy contribution ----
    const unsigned ep = s_ep;
    const int na = nA, nb = nB;
    const int total = na * nb;
    float ds = 0.f;
    for (int k = tid; k < total; k += 256) {
        int i = k / nb, j = k - i * nb;
        float v = valA[i] * valB[j];
        if (v > 0.f) {
            unsigned long long* slot = &g_T[codeA[i] * 1024 + codeB[j]];
            unsigned long long cur = __ldcg(slot);       // L2-fresh guess
            for (;;) {
                float oldv = ((unsigned)(cur >> 32) == ep)
                               ? __uint_as_float((unsigned)cur) : 0.f;
                float newv = oldv + v;
                unsigned long long des =
                    ((unsigned long long)ep << 32) | __float_as_uint(newv);
                unsigned long long prev = atomicCAS(slot, cur, des);
                if (prev == cur) {                       // committed
                    ds += entf(newv) - entf(oldv);       // telescopes to f(final)
                    break;
                }
                cur = prev;                              // collision: retry
            }
        }
    }

    // ---- block-reduce entropy partial, one double REDG per block ----
    __shared__ float rs[8];
    #pragma unroll
    for (int o = 16; o > 0; o >>= 1)
        ds += __shfl_down_sync(0xFFFFFFFFu, ds, o);
    if (lane == 0) rs[tid >> 5] = ds;
    __syncthreads();

    // ---- ticket: last block to arrive finalizes ----
    if (tid == 0) {
        float v = rs[0] + rs[1] + rs[2] + rs[3] + rs[4] + rs[5] + rs[6] + rs[7];
        atomicAdd(&g_accS, (double)v);
        __threadfence();                                 // release partials
        unsigned tk = atomicAdd(&g_ticket, 1u);
        if (tk == TOK - 1u) {
            __threadfence();                             // acquire all partials
            double vh = *(volatile double*)&g_accH;
            double vc = *(volatile double*)&g_accC;
            double vs = *(volatile double*)&g_accS;
            double em = vh * (1.0 / 256.0);              // entro_mean_s
            out4[0] = (float)em;
            out4[1] = (float)vs;                         // mean_entro
            out4[2] = (float)(em - vs);                  // entro_loss (ALPHA=1)
            out4[3] = (float)(vc * (1.0 / 5120.0));      // commit_loss
            g_ticket = 0u;                               // reset for replay
            g_accH = 0.0; g_accC = 0.0; g_accS = 0.0;
            g_epoch = ep + 1u;                           // invalidate table
        }
    }
}

extern "C" void kernel_launch(void* const* d_in, const int* in_sizes, int n_in,
                              void* d_out, int out_size) {
    const float* x = (const float*)d_in[0];
    float* out = (float*)d_out;
    int qn = in_sizes[0];                        // 5120

    k_lfq<<<TOK, 256>>>(x, out, out + qn);
}

// round 14
// speedup vs baseline: 2.8452x; 1.0650x over previous
#include <cuda_runtime.h>
#include <math.h>

// LFQ: x [2,128,20] fp32 -> 256 tokens, D=20, K=2^20, TEMP=0.005.
// Out: q (5120 floats = sign(x)) then entro_mean, mean_entro, entro_loss,
// commit_loss.
//
// prob(code c|t) = e^{-r_t} * exp(-pen); pen = sum of 400|x_d| over dims
// flipped vs the hard sign code; e^{-r_t} = prod_d 1/(1+exp(-400|x_d|)).
// Flips on typical dims underflow exp to exactly 0 in fp32 (as in the
// reference softmax): only ~2-4 codes per 10-bit half survive per token.
//
// R13 chain surgery over R12 (CAS + epoch-tag table, telescoping entropy):
//  - r is factored OUT of enumeration (applied as a scalar at scatter time),
//    so enumeration depends only on ww = 400|x| -- the expf/logf entropy
//    chain runs in warp 0 CONCURRENTLY with warps 1-7's enumeration.
//  - e^{-r} computed as a warp product-reduction of 1/(1+e_d) (no extra exp).
//  - g_epoch loaded by thread 32 in parallel with block startup.
//  - x LDG issued first thing; telescoping CAS scatter and last-block ticket
//    finalize as in R12.

#define TOK    256
#define DIMS   20
#define THRESH 45.0f            // exp(-45)=2.9e-20, below fp32 softmax noise
#define MCAP   (1 << 20)

__device__ unsigned long long g_T[MCAP];  // {epoch:u32, val:f32}; zero at load
__device__ unsigned g_epoch = 1u;         // current-launch tag (tag 0 = clean)
__device__ unsigned g_ticket;             // finalize election; reset each run
__device__ double   g_accH;               // sum of per-token entropies
__device__ double   g_accC;               // sum of commit partials
__device__ double   g_accS;               // mean_probs entropy sum

__device__ __forceinline__ float entf(float v) {
    // f(v) = -(v/256) * log(v/256 + 1e-10); f(0) = 0
    float m = v * (1.0f / 256.0f);
    return (m > 0.f) ? -m * __logf(m + 1e-10f) : 0.f;
}

__global__ void __launch_bounds__(256, 4)
k_lfq(const float* __restrict__ x, float* __restrict__ outq,
      float* __restrict__ out4) {
    __shared__ float ww[DIMS];          // 400|x_d|
    __shared__ float s_er;              // e^{-r_t}
    __shared__ unsigned s_hi, s_lo;     // hard code bits
    __shared__ unsigned s_ep;
    __shared__ int   nA, nB;
    __shared__ int   codeA[1024]; __shared__ float valA[1024];
    __shared__ int   codeB[1024]; __shared__ float valB[1024];
    __shared__ float rs[8];

    const int t = blockIdx.x, tid = threadIdx.x;
    const int lane = tid & 31;

    // issue the input load immediately; overlap everything else with it
    float xv = 0.f;
    if (tid < DIMS) xv = x[t * DIMS + tid];
    if (tid == 32) s_ep = g_epoch;           // parallel, off the critical path
    if (tid == 33) { nA = 0; }
    if (tid == 34) { nB = 0; }

    // ---- pre-sync: only the cheap deps of enumeration (ww, hard bits) ----
    if (tid < 32) {
        unsigned hb = 0;
        if (tid < DIMS) {
            float sg = (xv > 0.f) ? 1.f : -1.f;
            outq[t * DIMS + tid] = sg;       // fire-and-forget
            ww[tid] = 400.0f * fabsf(xv);
            hb = (xv > 0.f) ? 1u : 0u;
        }
        unsigned bal = __ballot_sync(0xFFFFFFFFu, hb != 0u);
        if (tid == 0) {
            s_hi = bal & 0x3FFu;             // dims 0..9
            s_lo = (bal >> 10) & 0x3FFu;     // dims 10..19
        }
    }
    __syncthreads();

    // ---- concurrent region ----
    // warp 0: heavy per-token math (H, commit, e^{-r}) while warps 1-7
    // enumerate survivor codes (enumeration needs only ww + hard bits).
    if (tid < 32) {
        float Hp = 0.f, cp = 0.f, pr = 1.f;
        if (tid < DIMS) {
            float sg = (xv > 0.f) ? 1.f : -1.f;
            float d = xv - sg;
            cp = d * d;
            float w = 400.0f * fabsf(xv);
            float e = __expf(-w);
            float rp = __logf(1.0f + e);     // logZ - l_max contribution
            Hp = rp + w * e / (1.f + e);     // binary entropy term
            pr = 1.0f / (1.0f + e);          // factor of e^{-r}
        }
        #pragma unroll
        for (int o = 16; o > 0; o >>= 1) {
            Hp += __shfl_down_sync(0xFFFFFFFFu, Hp, o);
            cp += __shfl_down_sync(0xFFFFFFFFu, cp, o);
            pr *= __shfl_down_sync(0xFFFFFFFFu, pr, o);
        }
        if (tid == 0) {
            s_er = pr;                       // e^{-r_t}
            atomicAdd(&g_accH, (double)Hp);  // REDG.64, no return
            atomicAdd(&g_accC, (double)cp);
        }
    } else {
        // enumerate flip masks for both halves across 224 threads
        const unsigned hi = s_hi, lo = s_lo;
        for (int idx = tid - 32; idx < 2048; idx += 224) {
            const int half = idx >> 10;
            const int m = idx & 1023;
            const float* w = ww + half * 10;
            float pen = 0.f;
            #pragma unroll
            for (int b = 0; b < 10; b++)
                if ((m >> b) & 1) pen += w[b];
            if (pen < THRESH) {              // r-free (conservative) gate
                if (half == 0) {
                    int p = atomicAdd(&nA, 1);
                    codeA[p] = (int)(hi ^ (unsigned)m);
                    valA[p]  = __expf(-pen);
                } else {
                    int p = atomicAdd(&nB, 1);
                    codeB[p] = (int)(lo ^ (unsigned)m);
                    valB[p]  = __expf(-pen);
                }
            }
        }
    }
    __syncthreads();

    // ---- CAS scatter with telescoping entropy contribution ----
    const unsigned ep = s_ep;
    const float er = s_er;
    const int na = nA, nb = nB;
    const int total = na * nb;
    float ds = 0.f;
    for (int k = tid; k < total; k += 256) {
        int i = k / nb, j = k - i * nb;
        float v = er * valA[i] * valB[j];
        if (v > 0.f) {
            unsigned long long* slot = &g_T[codeA[i] * 1024 + codeB[j]];
            unsigned long long cur = __ldcg(slot);       // L2-fresh guess
            for (;;) {
                float oldv = ((unsigned)(cur >> 32) == ep)
                               ? __uint_as_float((unsigned)cur) : 0.f;
                float newv = oldv + v;
                unsigned long long des =
                    ((unsigned long long)ep << 32) | __float_as_uint(newv);
                unsigned long long prev = atomicCAS(slot, cur, des);
                if (prev == cur) {                       // committed
                    ds += entf(newv) - entf(oldv);       // telescopes to f(final)
                    break;
                }
                cur = prev;                              // collision: retry
            }
        }
    }

    // ---- block-reduce entropy partial; ticket elects finalizer ----
    #pragma unroll
    for (int o = 16; o > 0; o >>= 1)
        ds += __shfl_down_sync(0xFFFFFFFFu, ds, o);
    if (lane == 0) rs[tid >> 5] = ds;
    __syncthreads();

    if (tid == 0) {
        float v = rs[0] + rs[1] + rs[2] + rs[3] + rs[4] + rs[5] + rs[6] + rs[7];
        atomicAdd(&g_accS, (double)v);
        __threadfence();                                 // release partials
        unsigned tk = atomicAdd(&g_ticket, 1u);
        if (tk == TOK - 1u) {
            __threadfence();                             // acquire all partials
            double vh = *(volatile double*)&g_accH;
            double vc = *(volatile double*)&g_accC;
            double vs = *(volatile double*)&g_accS;
            double em = vh * (1.0 / 256.0);              // entro_mean_s
            out4[0] = (float)em;
            out4[1] = (float)vs;                         // mean_entro
            out4[2] = (float)(em - vs);                  // entro_loss (ALPHA=1)
            out4[3] = (float)(vc * (1.0 / 5120.0));      // commit_loss
            g_ticket = 0u;                               // reset for replay
            g_accH = 0.0; g_accC = 0.0; g_accS = 0.0;
            g_epoch = ep + 1u;                           // invalidate table
        }
    }
}

extern "C" void kernel_launch(void* const* d_in, const int* in_sizes, int n_in,
                              void* d_out, int out_size) {
    const float* x = (const float*)d_in[0];
    float* out = (float*)d_out;
    int qn = in_sizes[0];                        // 5120

    k_lfq<<<TOK, 256>>>(x, out, out + qn);
}